// round 1
// baseline (speedup 1.0000x reference)
#include <cuda_runtime.h>

// Problem constants
#define BATCH 512
#define NIN   64
#define ADIM  64

// Device scratch (static __device__ arrays — no allocation)
__device__ float  g_W[64 * 2 * 64 * 64];     // exp(J_i^c) row-major [i][c][a][k]
__device__ float4 g_PT[31 * 4 * 1024];       // pair products, transposed+interleaved [(k>>2)*64+a] -> P[a][4k..4k+3]
__device__ float4 g_Last[2 * 1024];          // W_62^c in same layout
__device__ float  g_p[2 * 64];               // log p(x_63 | a', a_next=0) per variant

// log p(x | theta) for Bernoulli-logit: -max(t,0) + t*x - log1p(exp(-|t|))
__device__ __forceinline__ float lpv(float t, int c) {
    float s = -log1pf(expf(-fabsf(t)));
    return (c ? t : 0.0f) - fmaxf(t, 0.0f) + s;
}

// ---------------------------------------------------------------------------
// Kernel 1: compute W[i][c] = exp(log_px_mats + log_p_alpha) for i<63,
//           and g_p for i==63 (column 0 only, no log_p_alpha).
// grid = 128 (i*2+c), block = 256
// ---------------------------------------------------------------------------
__global__ void __launch_bounds__(256) k_prep(const float* __restrict__ theta,
                                              const float* __restrict__ u) {
    int bi  = blockIdx.x;
    int i   = bi >> 1;
    int c   = bi & 1;
    int tid = threadIdx.x;

    if (i == 63) {
        if (tid < 64) {
            float t = theta[63 * 4096 + tid * 64 + 0];
            g_p[c * 64 + tid] = lpv(t, c);
        }
        return;
    }

    __shared__ float slpa[64];
    if (tid < 32) {
        // log_softmax over the 64 entries of u[i]
        float u0 = u[i * 64 + tid];
        float u1 = u[i * 64 + tid + 32];
        float m = fmaxf(u0, u1);
        #pragma unroll
        for (int o = 16; o; o >>= 1) m = fmaxf(m, __shfl_xor_sync(0xffffffffu, m, o));
        float s = expf(u0 - m) + expf(u1 - m);
        #pragma unroll
        for (int o = 16; o; o >>= 1) s += __shfl_xor_sync(0xffffffffu, s, o);
        float lse = m + logf(s);
        slpa[tid]      = u0 - lse;
        slpa[tid + 32] = u1 - lse;
    }
    __syncthreads();

    float*       Wd = g_W + (i * 2 + c) * 4096;
    const float* Th = theta + i * 4096;
    #pragma unroll
    for (int e = 0; e < 16; ++e) {
        int idx = e * 256 + tid;           // idx = a*64 + k
        int k   = idx & 63;
        float t = Th[idx];
        Wd[idx] = expf(lpv(t, c) + slpa[k]);
    }
}

// ---------------------------------------------------------------------------
// Kernel 2: pair products P_t^{c0c1} = W[2t][c0] @ W[2t+1][c1] (linear domain,
// exact semiring combine), stored transposed+interleaved for the main kernel.
// Also re-layouts W[62][c] into g_Last.
// grid = 126 (124 pair blocks + 2 last-step blocks), block = 256
// ---------------------------------------------------------------------------
__global__ void __launch_bounds__(256) k_pair() {
    int blk = blockIdx.x;
    int tid = threadIdx.x;

    if (blk >= 124) {
        // relayout W[62][c]: dst[(k>>2)*64 + a] = {W[a][4q..4q+3]}
        int c = blk - 124;
        const float* src = g_W + (62 * 2 + c) * 4096;
        #pragma unroll
        for (int r = 0; r < 4; ++r) {
            int p = tid + 256 * r;         // 0..1023
            int a = p & 63;
            int q = p >> 6;                // 0..15
            float4 v = *reinterpret_cast<const float4*>(src + a * 64 + 4 * q);
            g_Last[c * 1024 + q * 64 + a] = v;
        }
        return;
    }

    int t  = blk >> 2;
    int vv = blk & 3;
    int c0 = vv >> 1;
    int c1 = vv & 1;
    const float* A  = g_W + ((2 * t) * 2 + c0) * 4096;       // W_{2t}^{c0}
    const float* Bm = g_W + ((2 * t + 1) * 2 + c1) * 4096;   // W_{2t+1}^{c1}

    __shared__ float sA[4096];
    __shared__ float sB[4096];
    #pragma unroll
    for (int r = 0; r < 16; ++r) {
        sA[tid + 256 * r] = A[tid + 256 * r];
        sB[tid + 256 * r] = Bm[tid + 256 * r];
    }
    __syncthreads();

    int a  = tid >> 2;        // output row
    int kq = tid & 3;
    int k0 = kq * 16;         // output cols k0..k0+15

    float acc[16];
    #pragma unroll
    for (int z = 0; z < 16; ++z) acc[z] = 0.0f;

    const float4* sB4 = reinterpret_cast<const float4*>(sB);
    for (int j = 0; j < 64; ++j) {
        float ra = sA[a * 64 + j];
        #pragma unroll
        for (int ii = 0; ii < 4; ++ii) {
            float4 b4 = sB4[j * 16 + (k0 >> 2) + ii];
            acc[ii * 4 + 0] = fmaf(ra, b4.x, acc[ii * 4 + 0]);
            acc[ii * 4 + 1] = fmaf(ra, b4.y, acc[ii * 4 + 1]);
            acc[ii * 4 + 2] = fmaf(ra, b4.z, acc[ii * 4 + 2]);
            acc[ii * 4 + 3] = fmaf(ra, b4.w, acc[ii * 4 + 3]);
        }
    }

    float4* dst = g_PT + (t * 4 + vv) * 1024;
    #pragma unroll
    for (int ii = 0; ii < 4; ++ii) {
        int q = (k0 >> 2) + ii;
        dst[q * 64 + a] = make_float4(acc[ii * 4 + 0], acc[ii * 4 + 1],
                                      acc[ii * 4 + 2], acc[ii * 4 + 3]);
    }
}

// ---------------------------------------------------------------------------
// Kernel 3: per-batch stabilized log-semiring matvec chain.
// v = p; v <- J_62 (x) v; then v <- P_t (x) v for t = 30..0. Output v.
// grid = 512 (one batch per CTA), block = 64 (thread a owns v[a]).
// ---------------------------------------------------------------------------
__global__ void __launch_bounds__(64) k_main(const float* __restrict__ x,
                                             float* __restrict__ out) {
    int b = blockIdx.x;
    int a = threadIdx.x;

    __shared__ float4   se4[16];
    __shared__ unsigned sbits[2];
    __shared__ float    red[2];

    float xa = x[b * 64 + a];
    unsigned bal = __ballot_sync(0xffffffffu, xa != 0.0f);
    if ((a & 31) == 0) sbits[a >> 5] = bal;
    __syncthreads();
    unsigned long long bits =
        ((unsigned long long)sbits[1] << 32) | (unsigned long long)sbits[0];

    int c63 = (int)((bits >> 63) & 1ULL);
    float v = g_p[c63 * 64 + a];

    float* se = reinterpret_cast<float*>(se4);

    #pragma unroll 1
    for (int s = 0; s < 32; ++s) {
        const float4* base;
        if (s == 0) {
            int c62 = (int)((bits >> 62) & 1ULL);
            base = g_Last + c62 * 1024;
        } else {
            int t  = 31 - s;                                   // 30 .. 0
            int vv = ((int)((bits >> (2 * t)) & 1ULL)) * 2
                   + ((int)((bits >> (2 * t + 1)) & 1ULL));
            base = g_PT + (t * 4 + vv) * 1024;
        }

        // block max of v (2 warps)
        float wm = v;
        #pragma unroll
        for (int o = 16; o; o >>= 1) wm = fmaxf(wm, __shfl_xor_sync(0xffffffffu, wm, o));
        __syncthreads();                    // protect red/se from prev-iter readers
        if ((a & 31) == 0) red[a >> 5] = wm;
        __syncthreads();
        float m = fmaxf(red[0], red[1]);

        se[a] = expf(v - m);
        __syncthreads();

        float4 acc = make_float4(0.f, 0.f, 0.f, 0.f);
        #pragma unroll
        for (int k4 = 0; k4 < 16; ++k4) {
            float4 w = __ldg(&base[k4 * 64 + a]);
            float4 e = se4[k4];
            acc.x = fmaf(w.x, e.x, acc.x);
            acc.y = fmaf(w.y, e.y, acc.y);
            acc.z = fmaf(w.z, e.z, acc.z);
            acc.w = fmaf(w.w, e.w, acc.w);
        }
        float ssum = (acc.x + acc.y) + (acc.z + acc.w);
        v = logf(ssum) + m;
    }

    out[b * 64 + a] = v;
}

// ---------------------------------------------------------------------------
extern "C" void kernel_launch(void* const* d_in, const int* in_sizes, int n_in,
                              void* d_out, int out_size) {
    const float* x     = nullptr;
    const float* theta = nullptr;
    const float* u     = nullptr;
    for (int i = 0; i < n_in; ++i) {
        if      (in_sizes[i] == BATCH * NIN)        x     = (const float*)d_in[i];
        else if (in_sizes[i] == NIN * ADIM * ADIM)  theta = (const float*)d_in[i];
        else if (in_sizes[i] == (NIN - 1) * ADIM)   u     = (const float*)d_in[i];
    }

    k_prep<<<128, 256>>>(theta, u);
    k_pair<<<126, 256>>>();
    k_main<<<BATCH, 64>>>(x, (float*)d_out);
}

// round 2
// speedup vs baseline: 1.5878x; 1.5878x over previous
#include <cuda_runtime.h>
#include <cuda_bf16.h>

#define BATCH 512
#define NIN   64
#define ADIM  64

// ---------------- device scratch (static, no allocation) -------------------
__device__ float4 g_W4[63 * 2 * 1024];   // exp(J_i^c), row-major [i][c][a][k], fp32
__device__ float4 g_P4[31 * 4 * 1024];   // pair products W_{2t}^{c0} @ W_{2t+1}^{c1}, row-major fp32
__device__ uint4  g_Q4[248 * 512];       // quads (240) + triple (8), bf16, chunk-transposed:
                                         //   mat*512 + q*64 + a, chunk q = 8 consecutive k (one uint4)
__device__ float  g_p[2 * 64];           // log p(x_63 | a', col 0), per variant c

// log p(x=c | theta) for Bernoulli-logit
__device__ __forceinline__ float lpv(float t, int c) {
    float s = __logf(1.0f + __expf(-fabsf(t)));
    return (c ? t : 0.0f) - fmaxf(t, 0.0f) - s;
}

// ---------------------------------------------------------------------------
// Kernel 1: W[i][c] = exp(log_px_mats[i][c] + log_p_alpha[i]) for i<63; g_p for i=63.
// grid = 505 (504 = 63*2*4 quarters + 1 tail), block = 256
// ---------------------------------------------------------------------------
__global__ void __launch_bounds__(256) k_prep(const float* __restrict__ theta,
                                              const float* __restrict__ u) {
    int blk = blockIdx.x, tid = threadIdx.x;

    if (blk == 504) {
        if (tid < 128) {
            int c = tid >> 6, aa = tid & 63;
            float t = theta[63 * 4096 + aa * 64];
            g_p[c * 64 + aa] = lpv(t, c);
        }
        return;
    }

    int i = blk >> 3, c = (blk >> 2) & 1, part = blk & 3;

    __shared__ float slpa[64];
    if (tid < 32) {
        float u0 = u[i * 64 + tid];
        float u1 = u[i * 64 + 32 + tid];
        float m = fmaxf(u0, u1);
        #pragma unroll
        for (int o = 16; o; o >>= 1) m = fmaxf(m, __shfl_xor_sync(0xffffffffu, m, o));
        float s = __expf(u0 - m) + __expf(u1 - m);
        #pragma unroll
        for (int o = 16; o; o >>= 1) s += __shfl_xor_sync(0xffffffffu, s, o);
        float lse = m + __logf(s);
        slpa[tid]      = u0 - lse;
        slpa[tid + 32] = u1 - lse;
    }
    __syncthreads();

    float4 t4 = reinterpret_cast<const float4*>(theta)[i * 1024 + part * 256 + tid];
    int k0 = (tid * 4) & 63;     // 4 consecutive k, never crossing a row
    float4 o;
    o.x = __expf(lpv(t4.x, c) + slpa[k0 + 0]);
    o.y = __expf(lpv(t4.y, c) + slpa[k0 + 1]);
    o.z = __expf(lpv(t4.z, c) + slpa[k0 + 2]);
    o.w = __expf(lpv(t4.w, c) + slpa[k0 + 3]);
    g_W4[(i * 2 + c) * 1024 + part * 256 + tid] = o;
}

// ---------------------------------------------------------------------------
// 64x64x64 fp32 GEMM: A rows in registers, B broadcast from smem (conflict-free).
// 256 threads: thread = (a = tid&63, seg = tid>>6), computes C[a][seg*16 .. +15].
// ---------------------------------------------------------------------------
__device__ __forceinline__ void gemm64(const float4* __restrict__ A4,
                                       const float4* __restrict__ B4,
                                       float* acc, float4* sB, int tid) {
    int a = tid & 63;
    int seg = tid >> 6;

    float4 ar[16];
    #pragma unroll
    for (int q = 0; q < 16; ++q) ar[q] = A4[a * 16 + q];

    #pragma unroll
    for (int r = 0; r < 4; ++r) sB[tid + 256 * r] = B4[tid + 256 * r];
    __syncthreads();

    #pragma unroll
    for (int z = 0; z < 16; ++z) acc[z] = 0.0f;

    #pragma unroll
    for (int j4 = 0; j4 < 16; ++j4) {
        float4 av = ar[j4];
        #pragma unroll
        for (int jj = 0; jj < 4; ++jj) {
            float s = (jj == 0) ? av.x : (jj == 1) ? av.y : (jj == 2) ? av.z : av.w;
            const float4* brow = sB + (j4 * 4 + jj) * 16 + seg * 4;
            #pragma unroll
            for (int ii = 0; ii < 4; ++ii) {
                float4 bv = brow[ii];
                acc[ii * 4 + 0] = fmaf(s, bv.x, acc[ii * 4 + 0]);
                acc[ii * 4 + 1] = fmaf(s, bv.y, acc[ii * 4 + 1]);
                acc[ii * 4 + 2] = fmaf(s, bv.z, acc[ii * 4 + 2]);
                acc[ii * 4 + 3] = fmaf(s, bv.w, acc[ii * 4 + 3]);
            }
        }
    }
}

// ---------------------------------------------------------------------------
// Kernel 2: pairs P_t^{(c0,c1)} = W_{2t}^{c0} @ W_{2t+1}^{c1}, fp32 row-major.
// grid = 124 (t = blk>>2 in 0..30, vv = blk&3), block = 256
// ---------------------------------------------------------------------------
__global__ void __launch_bounds__(256) k_pair() {
    __shared__ float4 sB[1024];
    int blk = blockIdx.x, tid = threadIdx.x;
    int t = blk >> 2, vv = blk & 3;
    const float4* A4 = g_W4 + ((2 * t)     * 2 + (vv >> 1)) * 1024;
    const float4* B4 = g_W4 + ((2 * t + 1) * 2 + (vv & 1))  * 1024;

    float acc[16];
    gemm64(A4, B4, acc, sB, tid);

    int a = tid & 63, seg = tid >> 6;
    float4* C4 = g_P4 + blk * 1024;
    #pragma unroll
    for (int ii = 0; ii < 4; ++ii)
        C4[a * 16 + seg * 4 + ii] =
            make_float4(acc[ii*4+0], acc[ii*4+1], acc[ii*4+2], acc[ii*4+3]);
}

// ---------------------------------------------------------------------------
// Kernel 3: quads Q_t^{v} = P_{2t}^{v>>2} @ P_{2t+1}^{v&3}  (blk = t*16+v, t<15)
//           triple T^{v} = P_30^{v>>1} @ W_62^{v&1}          (blk = 240+v, v<8)
// Output bf16 chunk-transposed for the main kernel.
// grid = 248, block = 256
// ---------------------------------------------------------------------------
__global__ void __launch_bounds__(256) k_quad() {
    __shared__ float4 sB[1024];
    int blk = blockIdx.x, tid = threadIdx.x;

    const float4 *A4, *B4;
    if (blk < 240) {
        int t = blk >> 4, v = blk & 15;
        A4 = g_P4 + ((2 * t)     * 4 + (v >> 2)) * 1024;
        B4 = g_P4 + ((2 * t + 1) * 4 + (v & 3))  * 1024;
    } else {
        int v = blk - 240;
        A4 = g_P4 + (30 * 4 + (v >> 1)) * 1024;
        B4 = g_W4 + (62 * 2 + (v & 1))  * 1024;
    }

    float acc[16];
    gemm64(A4, B4, acc, sB, tid);

    int a = tid & 63, seg = tid >> 6;
    uint4* D = g_Q4 + blk * 512;
    #pragma unroll
    for (int h = 0; h < 2; ++h) {
        int q = seg * 2 + h;
        __nv_bfloat162 p0 = __floats2bfloat162_rn(acc[h*8+0], acc[h*8+1]);
        __nv_bfloat162 p1 = __floats2bfloat162_rn(acc[h*8+2], acc[h*8+3]);
        __nv_bfloat162 p2 = __floats2bfloat162_rn(acc[h*8+4], acc[h*8+5]);
        __nv_bfloat162 p3 = __floats2bfloat162_rn(acc[h*8+6], acc[h*8+7]);
        uint4 uo;
        uo.x = *reinterpret_cast<unsigned*>(&p0);
        uo.y = *reinterpret_cast<unsigned*>(&p1);
        uo.z = *reinterpret_cast<unsigned*>(&p2);
        uo.w = *reinterpret_cast<unsigned*>(&p3);
        D[q * 64 + a] = uo;
    }
}

// ---------------------------------------------------------------------------
// Kernel 4: per-batch stabilized log-semiring chain over 16 bf16 matvecs.
// 1 warp per batch (no CTA barriers). Lane l owns rows l and l+32.
// grid = 256, block = 64 (2 warps = 2 batches per CTA)
// ---------------------------------------------------------------------------
__device__ __forceinline__ void unpack8(uint4 u, float* f) {
    float2 t;
    t = __bfloat1622float2(*reinterpret_cast<__nv_bfloat162*>(&u.x)); f[0]=t.x; f[1]=t.y;
    t = __bfloat1622float2(*reinterpret_cast<__nv_bfloat162*>(&u.y)); f[2]=t.x; f[3]=t.y;
    t = __bfloat1622float2(*reinterpret_cast<__nv_bfloat162*>(&u.z)); f[4]=t.x; f[5]=t.y;
    t = __bfloat1622float2(*reinterpret_cast<__nv_bfloat162*>(&u.w)); f[6]=t.x; f[7]=t.y;
}

__global__ void __launch_bounds__(64) k_main(const float* __restrict__ x,
                                             float* __restrict__ out) {
    int w = threadIdx.x >> 5, l = threadIdx.x & 31;
    int b = blockIdx.x * 2 + w;

    __shared__ float4 se4s[2][16];
    float* se = reinterpret_cast<float*>(se4s[w]);

    float x0 = x[b * 64 + l];
    float x1 = x[b * 64 + 32 + l];
    unsigned blo = __ballot_sync(0xffffffffu, x0 != 0.0f);
    unsigned bhi = __ballot_sync(0xffffffffu, x1 != 0.0f);
    unsigned long long bits = ((unsigned long long)bhi << 32) | (unsigned long long)blo;

    int c63 = (int)(bits >> 63) & 1;
    float v0 = g_p[c63 * 64 + l];
    float v1 = g_p[c63 * 64 + 32 + l];

    #pragma unroll 1
    for (int s = 0; s < 16; ++s) {
        int mat;
        if (s == 0) {
            mat = 240 + ((((int)(bits >> 60)) & 1) << 2)
                      + ((((int)(bits >> 61)) & 1) << 1)
                      +  (((int)(bits >> 62)) & 1);
        } else {
            int t = 15 - s;                       // 14 .. 0
            mat = t * 16
                + ((((int)(bits >> (4*t    ))) & 1) << 3)
                + ((((int)(bits >> (4*t + 1))) & 1) << 2)
                + ((((int)(bits >> (4*t + 2))) & 1) << 1)
                +  (((int)(bits >> (4*t + 3))) & 1);
        }
        const uint4* base = g_Q4 + mat * 512;

        // issue weight loads early; the max-reduction below hides L2 latency
        uint4 wr[16];
        #pragma unroll
        for (int q = 0; q < 8; ++q) {
            wr[q]     = base[q * 64 + l];
            wr[8 + q] = base[q * 64 + 32 + l];
        }

        float m = fmaxf(v0, v1);
        #pragma unroll
        for (int o = 16; o; o >>= 1) m = fmaxf(m, __shfl_xor_sync(0xffffffffu, m, o));

        se[l]      = __expf(v0 - m);
        se[l + 32] = __expf(v1 - m);
        __syncwarp();

        float4 a0 = make_float4(0.f, 0.f, 0.f, 0.f);
        float4 a1 = make_float4(0.f, 0.f, 0.f, 0.f);
        #pragma unroll
        for (int q = 0; q < 8; ++q) {
            float4 el = se4s[w][2 * q];
            float4 eh = se4s[w][2 * q + 1];
            float f[8];
            unpack8(wr[q], f);
            a0.x = fmaf(f[0], el.x, a0.x);  a0.y = fmaf(f[1], el.y, a0.y);
            a0.z = fmaf(f[2], el.z, a0.z);  a0.w = fmaf(f[3], el.w, a0.w);
            a0.x = fmaf(f[4], eh.x, a0.x);  a0.y = fmaf(f[5], eh.y, a0.y);
            a0.z = fmaf(f[6], eh.z, a0.z);  a0.w = fmaf(f[7], eh.w, a0.w);
            unpack8(wr[8 + q], f);
            a1.x = fmaf(f[0], el.x, a1.x);  a1.y = fmaf(f[1], el.y, a1.y);
            a1.z = fmaf(f[2], el.z, a1.z);  a1.w = fmaf(f[3], el.w, a1.w);
            a1.x = fmaf(f[4], eh.x, a1.x);  a1.y = fmaf(f[5], eh.y, a1.y);
            a1.z = fmaf(f[6], eh.z, a1.z);  a1.w = fmaf(f[7], eh.w, a1.w);
        }
        v0 = __logf((a0.x + a0.y) + (a0.z + a0.w)) + m;
        v1 = __logf((a1.x + a1.y) + (a1.z + a1.w)) + m;
        __syncwarp();
    }

    out[b * 64 + l]      = v0;
    out[b * 64 + 32 + l] = v1;
}

// ---------------------------------------------------------------------------
extern "C" void kernel_launch(void* const* d_in, const int* in_sizes, int n_in,
                              void* d_out, int out_size) {
    const float* x     = nullptr;
    const float* theta = nullptr;
    const float* u     = nullptr;
    for (int i = 0; i < n_in; ++i) {
        if      (in_sizes[i] == BATCH * NIN)       x     = (const float*)d_in[i];
        else if (in_sizes[i] == NIN * ADIM * ADIM) theta = (const float*)d_in[i];
        else if (in_sizes[i] == (NIN - 1) * ADIM)  u     = (const float*)d_in[i];
    }

    k_prep<<<505, 256>>>(theta, u);
    k_pair<<<124, 256>>>();
    k_quad<<<248, 256>>>();
    k_main<<<256, 64>>>(x, (float*)d_out);
}

// round 3
// speedup vs baseline: 1.8266x; 1.1504x over previous
#include <cuda_runtime.h>
#include <cuda_bf16.h>

#define BATCH 512
#define NIN   64
#define ADIM  64

// ---------------- device scratch (static, no allocation) -------------------
__device__ float4 g_P4[31 * 4 * 1024];   // pair products, row-major fp32 [mat][a*16+q]
__device__ uint4  g_Q4[248 * 512];       // quads(240)+triples(8), bf16, chunk layout:
                                         //   mat*512 + q*64 + row ; uint4 = row's k=8q..8q+7

// ---------------------------------------------------------------------------
// Kernel 1: fused prep+pair. CTA (t,vv) computes A=W_{2t}^{c0}, B=W_{2t+1}^{c1}
// inline from theta/u, then P = A@B (64^3 fp32). grid=124, block=256.
// W_i^c[a,k] = sigmoid_c(theta[i,a,k]) * softmax(u[i])[k]
// ---------------------------------------------------------------------------
__global__ void __launch_bounds__(256) k_pair(const float* __restrict__ theta,
                                              const float* __restrict__ u) {
    __shared__ float sAT[65 * 64];               // A transposed, stride 65 (conflict-free)
    __shared__ __align__(16) float sB[4096];     // B row-major
    __shared__ float expa[2][64];

    int blk = blockIdx.x, tid = threadIdx.x;
    int t = blk >> 2, vv = blk & 3;
    int i0 = 2 * t, i1 = 2 * t + 1, c0 = vv >> 1, c1 = vv & 1;
    int wid = tid >> 5, lane = tid & 31;

    if (wid < 2) {                               // softmax(u[i0]), softmax(u[i1])
        int i = i0 + wid;
        float u0 = u[i * 64 + lane], u1 = u[i * 64 + 32 + lane];
        float mm = fmaxf(u0, u1);
        #pragma unroll
        for (int o = 16; o; o >>= 1) mm = fmaxf(mm, __shfl_xor_sync(0xffffffffu, mm, o));
        float ss = __expf(u0 - mm) + __expf(u1 - mm);
        #pragma unroll
        for (int o = 16; o; o >>= 1) ss += __shfl_xor_sync(0xffffffffu, ss, o);
        float lse = mm + __logf(ss);
        expa[wid][lane]      = __expf(u0 - lse);
        expa[wid][lane + 32] = __expf(u1 - lse);
    }
    __syncthreads();

    #pragma unroll
    for (int r = 0; r < 16; ++r) {
        int idx = tid + 256 * r;                 // idx = row*64 + k
        int k = idx & 63, row = idx >> 6;
        float ta = theta[i0 * 4096 + idx];
        float sa = __fdividef(1.0f, 1.0f + __expf(-ta));
        sAT[k * 65 + row] = (c0 ? sa : 1.0f - sa) * expa[0][k];
        float tb = theta[i1 * 4096 + idx];
        float sb = __fdividef(1.0f, 1.0f + __expf(-tb));
        sB[idx] = (c1 ? sb : 1.0f - sb) * expa[1][k];
    }
    __syncthreads();

    int a = tid & 63, seg = tid >> 6;
    float ar[64];
    #pragma unroll
    for (int j = 0; j < 64; ++j) ar[j] = sAT[j * 65 + a];   // conflict-free

    float acc[16];
    #pragma unroll
    for (int z = 0; z < 16; ++z) acc[z] = 0.0f;
    #pragma unroll
    for (int j = 0; j < 64; ++j) {
        float s = ar[j];
        const float4* brow = reinterpret_cast<const float4*>(sB + j * 64) + seg * 4;
        #pragma unroll
        for (int ii = 0; ii < 4; ++ii) {
            float4 bv = brow[ii];                // uniform per warp (broadcast)
            acc[ii*4+0] = fmaf(s, bv.x, acc[ii*4+0]);
            acc[ii*4+1] = fmaf(s, bv.y, acc[ii*4+1]);
            acc[ii*4+2] = fmaf(s, bv.z, acc[ii*4+2]);
            acc[ii*4+3] = fmaf(s, bv.w, acc[ii*4+3]);
        }
    }

    float4* C4 = g_P4 + blk * 1024;
    #pragma unroll
    for (int ii = 0; ii < 4; ++ii)
        C4[a * 16 + seg * 4 + ii] =
            make_float4(acc[ii*4+0], acc[ii*4+1], acc[ii*4+2], acc[ii*4+3]);
}

// ---------------------------------------------------------------------------
// Kernel 2: quads Q = P_{2t}^{v>>2} @ P_{2t+1}^{v&3} (blk<240);
//           triples T = P_30^{v>>1} @ W62^{v&1} (blk 240..247, W62 inline).
// Output bf16 chunk layout for k_main. grid=248, block=256.
// ---------------------------------------------------------------------------
__global__ void __launch_bounds__(256) k_quad(const float* __restrict__ theta,
                                              const float* __restrict__ u) {
    __shared__ __align__(16) float4 sB[1024];
    __shared__ float expa[64];
    int blk = blockIdx.x, tid = threadIdx.x;

    const float4* A4;
    if (blk < 240) {
        int t = blk >> 4, v = blk & 15;
        A4 = g_P4 + ((2 * t) * 4 + (v >> 2)) * 1024;
        const float4* B4 = g_P4 + ((2 * t + 1) * 4 + (v & 3)) * 1024;
        #pragma unroll
        for (int r = 0; r < 4; ++r) sB[tid + 256 * r] = B4[tid + 256 * r];
    } else {
        int v = blk - 240;
        A4 = g_P4 + (30 * 4 + (v >> 1)) * 1024;
        int c = v & 1;
        if (tid < 32) {                          // softmax(u[62])
            float u0 = u[62 * 64 + tid], u1 = u[62 * 64 + 32 + tid];
            float mm = fmaxf(u0, u1);
            #pragma unroll
            for (int o = 16; o; o >>= 1) mm = fmaxf(mm, __shfl_xor_sync(0xffffffffu, mm, o));
            float ss = __expf(u0 - mm) + __expf(u1 - mm);
            #pragma unroll
            for (int o = 16; o; o >>= 1) ss += __shfl_xor_sync(0xffffffffu, ss, o);
            float lse = mm + __logf(ss);
            expa[tid]      = __expf(u0 - lse);
            expa[tid + 32] = __expf(u1 - lse);
        }
        __syncthreads();
        float* sBf = reinterpret_cast<float*>(sB);
        #pragma unroll
        for (int r = 0; r < 16; ++r) {
            int idx = tid + 256 * r;
            float th = theta[62 * 4096 + idx];
            float sg = __fdividef(1.0f, 1.0f + __expf(-th));
            sBf[idx] = (c ? sg : 1.0f - sg) * expa[idx & 63];
        }
    }
    __syncthreads();

    int a = tid & 63, seg = tid >> 6;
    float4 ar4[16];
    #pragma unroll
    for (int q = 0; q < 16; ++q) ar4[q] = A4[a * 16 + q];

    float acc[16];
    #pragma unroll
    for (int z = 0; z < 16; ++z) acc[z] = 0.0f;
    #pragma unroll
    for (int j4 = 0; j4 < 16; ++j4) {
        float4 av = ar4[j4];
        #pragma unroll
        for (int jj = 0; jj < 4; ++jj) {
            float s = (jj == 0) ? av.x : (jj == 1) ? av.y : (jj == 2) ? av.z : av.w;
            const float4* brow = sB + (j4 * 4 + jj) * 16 + seg * 4;
            #pragma unroll
            for (int ii = 0; ii < 4; ++ii) {
                float4 bv = brow[ii];
                acc[ii*4+0] = fmaf(s, bv.x, acc[ii*4+0]);
                acc[ii*4+1] = fmaf(s, bv.y, acc[ii*4+1]);
                acc[ii*4+2] = fmaf(s, bv.z, acc[ii*4+2]);
                acc[ii*4+3] = fmaf(s, bv.w, acc[ii*4+3]);
            }
        }
    }

    uint4* D = g_Q4 + blk * 512;
    #pragma unroll
    for (int h = 0; h < 2; ++h) {
        int q = seg * 2 + h;
        __nv_bfloat162 p0 = __floats2bfloat162_rn(acc[h*8+0], acc[h*8+1]);
        __nv_bfloat162 p1 = __floats2bfloat162_rn(acc[h*8+2], acc[h*8+3]);
        __nv_bfloat162 p2 = __floats2bfloat162_rn(acc[h*8+4], acc[h*8+5]);
        __nv_bfloat162 p3 = __floats2bfloat162_rn(acc[h*8+6], acc[h*8+7]);
        uint4 uo;
        uo.x = *reinterpret_cast<unsigned*>(&p0);
        uo.y = *reinterpret_cast<unsigned*>(&p1);
        uo.z = *reinterpret_cast<unsigned*>(&p2);
        uo.w = *reinterpret_cast<unsigned*>(&p3);
        D[q * 64 + a] = uo;
    }
}

// ---------------------------------------------------------------------------
// Kernel 3: per-batch stabilized log-semiring chain, 16 steps.
// CTA = 64 threads = 1 batch, lane = row. Weight prefetch one step ahead;
// max refreshed every 2 steps (row sums < 1 => stale max is a safe upper bound).
// grid = 512, block = 64.
// ---------------------------------------------------------------------------
__device__ __forceinline__ int matq(unsigned long long bits, int t) {
    unsigned nib = (unsigned)(bits >> (4 * t)) & 0xFu;
    unsigned v = ((nib & 1u) << 3) | ((nib & 2u) << 1) | ((nib & 4u) >> 1) | ((nib & 8u) >> 3);
    return t * 16 + (int)v;
}

__device__ __forceinline__ float dotstep(const uint4* wr, const float4* e4) {
    float acc = 0.0f;
    #pragma unroll
    for (int q = 0; q < 8; ++q) {
        float4 e0 = e4[2 * q], e1 = e4[2 * q + 1];
        uint4 uw = wr[q];
        acc = fmaf(__uint_as_float(uw.x << 16),          e0.x, acc);
        acc = fmaf(__uint_as_float(uw.x & 0xffff0000u),  e0.y, acc);
        acc = fmaf(__uint_as_float(uw.y << 16),          e0.z, acc);
        acc = fmaf(__uint_as_float(uw.y & 0xffff0000u),  e0.w, acc);
        acc = fmaf(__uint_as_float(uw.z << 16),          e1.x, acc);
        acc = fmaf(__uint_as_float(uw.z & 0xffff0000u),  e1.y, acc);
        acc = fmaf(__uint_as_float(uw.w << 16),          e1.z, acc);
        acc = fmaf(__uint_as_float(uw.w & 0xffff0000u),  e1.w, acc);
    }
    return acc;
}

__global__ void __launch_bounds__(64) k_main(const float* __restrict__ x,
                                             const float* __restrict__ theta,
                                             float* __restrict__ out) {
    int tid = threadIdx.x, w = tid >> 5, l = tid & 31;
    int b = blockIdx.x;

    __shared__ __align__(16) float se[2][64];
    __shared__ float red[2];
    __shared__ unsigned sbits[2];

    float xa = x[b * 64 + tid];
    unsigned bal = __ballot_sync(0xffffffffu, xa != 0.0f);
    if (l == 0) sbits[w] = bal;
    __syncthreads();
    unsigned long long bits =
        ((unsigned long long)sbits[1] << 32) | (unsigned long long)sbits[0];

    // v init: log p(x63 | a, col 0)
    int c63 = (int)(bits >> 63) & 1;
    float t63 = theta[63 * 4096 + tid * 64];
    float v = (c63 ? t63 : 0.0f) - fmaxf(t63, 0.0f)
            - __logf(1.0f + __expf(-fabsf(t63)));

    // prefetch step 0 (triple)
    int m0 = 240 + (((int)(bits >> 60) & 1) << 2)
                 + (((int)(bits >> 61) & 1) << 1)
                 +  ((int)(bits >> 62) & 1);
    uint4 wrA[8], wrB[8];
    {
        const uint4* base = g_Q4 + m0 * 512;
        #pragma unroll
        for (int q = 0; q < 8; ++q) wrA[q] = base[q * 64 + tid];
    }

    float m = 0.0f;
    #pragma unroll 1
    for (int sp = 0; sp < 8; ++sp) {
        // ---- even step (s=2sp): compute with wrA, prefetch wrB, refresh max ----
        {
            const uint4* nb = g_Q4 + matq(bits, 14 - 2 * sp) * 512;
            #pragma unroll
            for (int q = 0; q < 8; ++q) wrB[q] = nb[q * 64 + tid];

            float wm = v;
            #pragma unroll
            for (int o = 16; o; o >>= 1) wm = fmaxf(wm, __shfl_xor_sync(0xffffffffu, wm, o));
            if (l == 0) red[w] = wm;
            __syncthreads();
            m = fmaxf(red[0], red[1]);
            se[0][tid] = __expf(v - m);
            __syncthreads();
            v = __logf(dotstep(wrA, reinterpret_cast<const float4*>(se[0]))) + m;
        }
        // ---- odd step (s=2sp+1): compute with wrB, prefetch wrA, stale max ----
        {
            if (sp < 7) {
                const uint4* nb = g_Q4 + matq(bits, 13 - 2 * sp) * 512;
                #pragma unroll
                for (int q = 0; q < 8; ++q) wrA[q] = nb[q * 64 + tid];
            }
            se[1][tid] = __expf(v - m);
            __syncthreads();
            v = __logf(dotstep(wrB, reinterpret_cast<const float4*>(se[1]))) + m;
        }
    }

    out[b * 64 + tid] = v;
}

// ---------------------------------------------------------------------------
extern "C" void kernel_launch(void* const* d_in, const int* in_sizes, int n_in,
                              void* d_out, int out_size) {
    const float* x     = nullptr;
    const float* theta = nullptr;
    const float* u     = nullptr;
    for (int i = 0; i < n_in; ++i) {
        if      (in_sizes[i] == BATCH * NIN)       x     = (const float*)d_in[i];
        else if (in_sizes[i] == NIN * ADIM * ADIM) theta = (const float*)d_in[i];
        else if (in_sizes[i] == (NIN - 1) * ADIM)  u     = (const float*)d_in[i];
    }

    k_pair<<<124, 256>>>(theta, u);
    k_quad<<<248, 256>>>(theta, u);
    k_main<<<BATCH, 64>>>(x, theta, (float*)d_out);
}

// round 5
// speedup vs baseline: 1.9623x; 1.0743x over previous
#include <cuda_runtime.h>
#include <cuda_bf16.h>

#define BATCH 512
#define NIN   64
#define ADIM  64

// ---------------- device scratch (static, no allocation) -------------------
__device__ float4 g_P4[31 * 4 * 1024];   // pair products, row-major fp32 [mat][a*16+q]
__device__ uint4  g_Q4[248 * 512];       // quads(240)+triples(8), bf16, chunk layout:
                                         //   mat*512 + q*64 + row ; uint4 = row's k=8q..8q+7

#define ASTR 65                          // padded row stride for A in smem

// ---------------------------------------------------------------------------
// Kernel 1: fused prep+pair. CTA (t,vv) computes A=W_{2t}^{c0}, B=W_{2t+1}^{c1}
// inline from theta/u, then P = A@B (64^3 fp32). grid=124, block=512.
// W_i^c[a,k] = sigmoid_c(theta[i,a,k]) * softmax(u[i])[k]
// A stored row-major padded (stride 65): read sA[a*65+j] = A[a][j], conflict-free.
// ---------------------------------------------------------------------------
__global__ void __launch_bounds__(512) k_pair(const float* __restrict__ theta,
                                              const float* __restrict__ u) {
    __shared__ float sA[64 * ASTR];
    __shared__ __align__(16) float sB[4096];
    __shared__ float expa[2][64];

    int blk = blockIdx.x, tid = threadIdx.x;
    int t = blk >> 2, vv = blk & 3;
    int i0 = 2 * t, i1 = 2 * t + 1, c0 = vv >> 1, c1 = vv & 1;
    int wid = tid >> 5, lane = tid & 31;

    if (wid < 2) {                               // softmax(u[i0]), softmax(u[i1])
        int i = i0 + wid;
        float u0 = u[i * 64 + lane], u1 = u[i * 64 + 32 + lane];
        float mm = fmaxf(u0, u1);
        #pragma unroll
        for (int o = 16; o; o >>= 1) mm = fmaxf(mm, __shfl_xor_sync(0xffffffffu, mm, o));
        float ss = __expf(u0 - mm) + __expf(u1 - mm);
        #pragma unroll
        for (int o = 16; o; o >>= 1) ss += __shfl_xor_sync(0xffffffffu, ss, o);
        float lse = mm + __logf(ss);
        expa[wid][lane]      = __expf(u0 - lse);
        expa[wid][lane + 32] = __expf(u1 - lse);
    }
    __syncthreads();

    const float4* th4 = reinterpret_cast<const float4*>(theta);
    float4* sB4 = reinterpret_cast<float4*>(sB);
    #pragma unroll
    for (int r = 0; r < 2; ++r) {
        int idx4 = tid + 512 * r;                // float4 index 0..1023
        int row = idx4 >> 4;
        int k0  = (idx4 * 4) & 63;
        float4 ta = th4[i0 * 1024 + idx4];
        { float s = __fdividef(1.0f, 1.0f + __expf(-ta.x)); sA[row * ASTR + k0 + 0] = (c0 ? s : 1.0f - s) * expa[0][k0 + 0]; }
        { float s = __fdividef(1.0f, 1.0f + __expf(-ta.y)); sA[row * ASTR + k0 + 1] = (c0 ? s : 1.0f - s) * expa[0][k0 + 1]; }
        { float s = __fdividef(1.0f, 1.0f + __expf(-ta.z)); sA[row * ASTR + k0 + 2] = (c0 ? s : 1.0f - s) * expa[0][k0 + 2]; }
        { float s = __fdividef(1.0f, 1.0f + __expf(-ta.w)); sA[row * ASTR + k0 + 3] = (c0 ? s : 1.0f - s) * expa[0][k0 + 3]; }
        float4 tb = th4[i1 * 1024 + idx4];
        float4 ob;
        { float s = __fdividef(1.0f, 1.0f + __expf(-tb.x)); ob.x = (c1 ? s : 1.0f - s) * expa[1][k0 + 0]; }
        { float s = __fdividef(1.0f, 1.0f + __expf(-tb.y)); ob.y = (c1 ? s : 1.0f - s) * expa[1][k0 + 1]; }
        { float s = __fdividef(1.0f, 1.0f + __expf(-tb.z)); ob.z = (c1 ? s : 1.0f - s) * expa[1][k0 + 2]; }
        { float s = __fdividef(1.0f, 1.0f + __expf(-tb.w)); ob.w = (c1 ? s : 1.0f - s) * expa[1][k0 + 3]; }
        sB4[idx4] = ob;
    }
    __syncthreads();

    int a = tid & 63, seg = tid >> 6;            // row a, cols seg*8 .. seg*8+7
    float acc[8];
    #pragma unroll
    for (int z = 0; z < 8; ++z) acc[z] = 0.0f;

    #pragma unroll
    for (int j = 0; j < 64; ++j) {
        float s = sA[a * ASTR + j];              // A[a][j], conflict-free (65 ≡ 1 mod 32)
        float4 b0 = sB4[j * 16 + seg * 2];       // warp-uniform: broadcast
        float4 b1 = sB4[j * 16 + seg * 2 + 1];
        acc[0] = fmaf(s, b0.x, acc[0]);  acc[1] = fmaf(s, b0.y, acc[1]);
        acc[2] = fmaf(s, b0.z, acc[2]);  acc[3] = fmaf(s, b0.w, acc[3]);
        acc[4] = fmaf(s, b1.x, acc[4]);  acc[5] = fmaf(s, b1.y, acc[5]);
        acc[6] = fmaf(s, b1.z, acc[6]);  acc[7] = fmaf(s, b1.w, acc[7]);
    }

    float4* C4 = g_P4 + blk * 1024;
    C4[a * 16 + seg * 2]     = make_float4(acc[0], acc[1], acc[2], acc[3]);
    C4[a * 16 + seg * 2 + 1] = make_float4(acc[4], acc[5], acc[6], acc[7]);
}

// ---------------------------------------------------------------------------
// Kernel 2: quads Q = P_{2t}^{v>>2} @ P_{2t+1}^{v&3} (blk<240);
//           triples T = P_30^{v>>1} @ W62^{v&1} (blk 240..247, W62 inline).
// Output bf16 chunk layout for k_main. grid=248, block=512.
// ---------------------------------------------------------------------------
__global__ void __launch_bounds__(512) k_quad(const float* __restrict__ theta,
                                              const float* __restrict__ u) {
    __shared__ float sA[64 * ASTR];
    __shared__ __align__(16) float sB[4096];
    __shared__ float expa[64];
    int blk = blockIdx.x, tid = threadIdx.x;

    float4* sB4 = reinterpret_cast<float4*>(sB);

    if (blk < 240) {
        int t = blk >> 4, v = blk & 15;
        const float4* A4 = g_P4 + ((2 * t)     * 4 + (v >> 2)) * 1024;
        const float4* B4 = g_P4 + ((2 * t + 1) * 4 + (v & 3))  * 1024;
        #pragma unroll
        for (int r = 0; r < 2; ++r) {
            int idx4 = tid + 512 * r;            // = row*16 + q
            int row = idx4 >> 4, k0 = (idx4 & 15) * 4;
            float4 av = A4[idx4];
            sA[row * ASTR + k0 + 0] = av.x;
            sA[row * ASTR + k0 + 1] = av.y;
            sA[row * ASTR + k0 + 2] = av.z;
            sA[row * ASTR + k0 + 3] = av.w;
            sB4[idx4] = B4[idx4];
        }
    } else {
        int v = blk - 240;
        const float4* A4 = g_P4 + (30 * 4 + (v >> 1)) * 1024;
        #pragma unroll
        for (int r = 0; r < 2; ++r) {
            int idx4 = tid + 512 * r;
            int row = idx4 >> 4, k0 = (idx4 & 15) * 4;
            float4 av = A4[idx4];
            sA[row * ASTR + k0 + 0] = av.x;
            sA[row * ASTR + k0 + 1] = av.y;
            sA[row * ASTR + k0 + 2] = av.z;
            sA[row * ASTR + k0 + 3] = av.w;
        }
        int c = v & 1;
        if (tid < 32) {                          // softmax(u[62])
            float u0 = u[62 * 64 + tid], u1 = u[62 * 64 + 32 + tid];
            float mm = fmaxf(u0, u1);
            #pragma unroll
            for (int o = 16; o; o >>= 1) mm = fmaxf(mm, __shfl_xor_sync(0xffffffffu, mm, o));
            float ss = __expf(u0 - mm) + __expf(u1 - mm);
            #pragma unroll
            for (int o = 16; o; o >>= 1) ss += __shfl_xor_sync(0xffffffffu, ss, o);
            float lse = mm + __logf(ss);
            expa[tid]      = __expf(u0 - lse);
            expa[tid + 32] = __expf(u1 - lse);
        }
        __syncthreads();
        const float4* th4 = reinterpret_cast<const float4*>(theta);
        #pragma unroll
        for (int r = 0; r < 2; ++r) {
            int idx4 = tid + 512 * r;
            int k0 = (idx4 * 4) & 63;
            float4 tb = th4[62 * 1024 + idx4];
            float4 ob;
            { float s = __fdividef(1.0f, 1.0f + __expf(-tb.x)); ob.x = (c ? s : 1.0f - s) * expa[k0 + 0]; }
            { float s = __fdividef(1.0f, 1.0f + __expf(-tb.y)); ob.y = (c ? s : 1.0f - s) * expa[k0 + 1]; }
            { float s = __fdividef(1.0f, 1.0f + __expf(-tb.z)); ob.z = (c ? s : 1.0f - s) * expa[k0 + 2]; }
            { float s = __fdividef(1.0f, 1.0f + __expf(-tb.w)); ob.w = (c ? s : 1.0f - s) * expa[k0 + 3]; }
            sB4[idx4] = ob;
        }
    }
    __syncthreads();

    int a = tid & 63, seg = tid >> 6;            // row a, cols seg*8 .. seg*8+7
    float acc[8];
    #pragma unroll
    for (int z = 0; z < 8; ++z) acc[z] = 0.0f;

    #pragma unroll
    for (int j = 0; j < 64; ++j) {
        float s = sA[a * ASTR + j];              // A[a][j], conflict-free
        float4 b0 = sB4[j * 16 + seg * 2];
        float4 b1 = sB4[j * 16 + seg * 2 + 1];
        acc[0] = fmaf(s, b0.x, acc[0]);  acc[1] = fmaf(s, b0.y, acc[1]);
        acc[2] = fmaf(s, b0.z, acc[2]);  acc[3] = fmaf(s, b0.w, acc[3]);
        acc[4] = fmaf(s, b1.x, acc[4]);  acc[5] = fmaf(s, b1.y, acc[5]);
        acc[6] = fmaf(s, b1.z, acc[6]);  acc[7] = fmaf(s, b1.w, acc[7]);
    }

    __nv_bfloat162 p0 = __floats2bfloat162_rn(acc[0], acc[1]);
    __nv_bfloat162 p1 = __floats2bfloat162_rn(acc[2], acc[3]);
    __nv_bfloat162 p2 = __floats2bfloat162_rn(acc[4], acc[5]);
    __nv_bfloat162 p3 = __floats2bfloat162_rn(acc[6], acc[7]);
    uint4 uo;
    uo.x = *reinterpret_cast<unsigned*>(&p0);
    uo.y = *reinterpret_cast<unsigned*>(&p1);
    uo.z = *reinterpret_cast<unsigned*>(&p2);
    uo.w = *reinterpret_cast<unsigned*>(&p3);
    g_Q4[blk * 512 + seg * 64 + a] = uo;
}

// ---------------------------------------------------------------------------
// Kernel 3: per-batch stabilized log-semiring chain, 16 steps.
// CTA = 64 threads = 1 batch, lane = row. Weight prefetch one step ahead;
// max refreshed every 2 steps (row sums < 1 => stale max is a safe upper bound).
// 8 parallel accumulators keep the dot's RAW chain short.
// grid = 512, block = 64.
// ---------------------------------------------------------------------------
__device__ __forceinline__ int matq(unsigned long long bits, int t) {
    unsigned nib = (unsigned)(bits >> (4 * t)) & 0xFu;
    unsigned v = ((nib & 1u) << 3) | ((nib & 2u) << 1) | ((nib & 4u) >> 1) | ((nib & 8u) >> 3);
    return t * 16 + (int)v;
}

__device__ __forceinline__ float dotstep(const uint4* wr, const float4* e4) {
    float a0 = 0.f, a1 = 0.f, a2 = 0.f, a3 = 0.f;
    float a4 = 0.f, a5 = 0.f, a6 = 0.f, a7 = 0.f;
    #pragma unroll
    for (int q = 0; q < 8; ++q) {
        float4 e0 = e4[2 * q], e1 = e4[2 * q + 1];
        uint4 uw = wr[q];
        a0 = fmaf(__uint_as_float(uw.x << 16),          e0.x, a0);
        a1 = fmaf(__uint_as_float(uw.x & 0xffff0000u),  e0.y, a1);
        a2 = fmaf(__uint_as_float(uw.y << 16),          e0.z, a2);
        a3 = fmaf(__uint_as_float(uw.y & 0xffff0000u),  e0.w, a3);
        a4 = fmaf(__uint_as_float(uw.z << 16),          e1.x, a4);
        a5 = fmaf(__uint_as_float(uw.z & 0xffff0000u),  e1.y, a5);
        a6 = fmaf(__uint_as_float(uw.w << 16),          e1.z, a6);
        a7 = fmaf(__uint_as_float(uw.w & 0xffff0000u),  e1.w, a7);
    }
    return ((a0 + a1) + (a2 + a3)) + ((a4 + a5) + (a6 + a7));
}

__global__ void __launch_bounds__(64) k_main(const float* __restrict__ x,
                                             const float* __restrict__ theta,
                                             float* __restrict__ out) {
    int tid = threadIdx.x, w = tid >> 5, l = tid & 31;
    int b = blockIdx.x;

    __shared__ __align__(16) float se[2][64];
    __shared__ float red[2];
    __shared__ unsigned sbits[2];

    float xa = x[b * 64 + tid];
    unsigned bal = __ballot_sync(0xffffffffu, xa != 0.0f);
    if (l == 0) sbits[w] = bal;
    __syncthreads();
    unsigned long long bits =
        ((unsigned long long)sbits[1] << 32) | (unsigned long long)sbits[0];

    // v init: log p(x63 | a, col 0)
    int c63 = (int)(bits >> 63) & 1;
    float t63 = theta[63 * 4096 + tid * 64];
    float v = (c63 ? t63 : 0.0f) - fmaxf(t63, 0.0f)
            - __logf(1.0f + __expf(-fabsf(t63)));

    // prefetch step 0 (triple)
    int m0 = 240 + (((int)(bits >> 60) & 1) << 2)
                 + (((int)(bits >> 61) & 1) << 1)
                 +  ((int)(bits >> 62) & 1);
    uint4 wrA[8], wrB[8];
    {
        const uint4* base = g_Q4 + m0 * 512;
        #pragma unroll
        for (int q = 0; q < 8; ++q) wrA[q] = base[q * 64 + tid];
    }

    float m = 0.0f;
    #pragma unroll 1
    for (int sp = 0; sp < 8; ++sp) {
        // ---- even step (s=2sp): compute with wrA, prefetch wrB, refresh max ----
        {
            const uint4* nb = g_Q4 + matq(bits, 14 - 2 * sp) * 512;
            #pragma unroll
            for (int q = 0; q < 8; ++q) wrB[q] = nb[q * 64 + tid];

            float wm = v;
            #pragma unroll
            for (int o = 16; o; o >>= 1) wm = fmaxf(wm, __shfl_xor_sync(0xffffffffu, wm, o));
            if (l == 0) red[w] = wm;
            __syncthreads();
            m = fmaxf(red[0], red[1]);
            se[0][tid] = __expf(v - m);
            __syncthreads();
            v = __logf(dotstep(wrA, reinterpret_cast<const float4*>(se[0]))) + m;
        }
        // ---- odd step (s=2sp+1): compute with wrB, prefetch wrA, stale max ----
        {
            if (sp < 7) {
                const uint4* nb = g_Q4 + matq(bits, 13 - 2 * sp) * 512;
                #pragma unroll
                for (int q = 0; q < 8; ++q) wrA[q] = nb[q * 64 + tid];
            }
            se[1][tid] = __expf(v - m);
            __syncthreads();
            v = __logf(dotstep(wrB, reinterpret_cast<const float4*>(se[1]))) + m;
        }
    }

    out[b * 64 + tid] = v;
}

// ---------------------------------------------------------------------------
extern "C" void kernel_launch(void* const* d_in, const int* in_sizes, int n_in,
                              void* d_out, int out_size) {
    const float* x     = nullptr;
    const float* theta = nullptr;
    const float* u     = nullptr;
    for (int i = 0; i < n_in; ++i) {
        if      (in_sizes[i] == BATCH * NIN)       x     = (const float*)d_in[i];
        else if (in_sizes[i] == NIN * ADIM * ADIM) theta = (const float*)d_in[i];
        else if (in_sizes[i] == (NIN - 1) * ADIM)  u     = (const float*)d_in[i];
    }

    k_pair<<<124, 512>>>(theta, u);
    k_quad<<<248, 512>>>(theta, u);
    k_main<<<BATCH, 64>>>(x, theta, (float*)d_out);
}

// round 6
// speedup vs baseline: 2.0000x; 1.0192x over previous
#include <cuda_runtime.h>
#include <cuda_bf16.h>

#define BATCH 512
#define NIN   64
#define ADIM  64

typedef unsigned long long ull;

// ---------------- device scratch (static, no allocation) -------------------
__device__ float4 g_P4[31 * 4 * 1024];   // pair products, row-major fp32 [mat][a*16+q]
__device__ uint4  g_Q4[248 * 512];       // quads(240)+triples(8), bf16, chunk layout:
                                         //   mat*512 + q*64 + row ; uint4 = row's k=8q..8q+7

#define AST4 17                          // A row stride in float4 units (68 floats)

// ---- packed f32x2 helpers (sm_103a) ---------------------------------------
__device__ __forceinline__ void ffma2(ull& d, ull a, ull b) {
    asm("fma.rn.f32x2 %0, %1, %2, %0;" : "+l"(d) : "l"(a), "l"(b));
}
__device__ __forceinline__ ull pk2(float x, float y) {
    ull r; asm("mov.b64 %0, {%1, %2};" : "=l"(r) : "f"(x), "f"(y)); return r;
}
__device__ __forceinline__ void up2(ull v, float& x, float& y) {
    asm("mov.b64 {%0, %1}, %2;" : "=f"(x), "=f"(y) : "l"(v));
}

// 64x64x64 GEMM consumer: A in padded-f4 smem (stride AST4), B row-major f4.
// thread = (a = tid&63, seg = tid>>6); computes C[a][seg*8 .. seg*8+7].
__device__ __forceinline__ void gemm_inner(const float4* sA4, const float4* sB4,
                                           int a, int seg, float* out8) {
    ull c0 = 0, c1 = 0, c2 = 0, c3 = 0;
    const float4* ap = sA4 + a * AST4;
    const ull*    bp = reinterpret_cast<const ull*>(sB4 + seg * 2);
    #pragma unroll
    for (int j4 = 0; j4 < 16; ++j4) {
        float4 av = ap[j4];
        #pragma unroll
        for (int jj = 0; jj < 4; ++jj) {
            float s = (jj == 0) ? av.x : (jj == 1) ? av.y : (jj == 2) ? av.z : av.w;
            ull ss = pk2(s, s);
            const ull* br = bp + (j4 * 4 + jj) * 32;   // 16 f4 per row = 32 u64
            ffma2(c0, ss, br[0]);
            ffma2(c1, ss, br[1]);
            ffma2(c2, ss, br[2]);
            ffma2(c3, ss, br[3]);
        }
    }
    up2(c0, out8[0], out8[1]);
    up2(c1, out8[2], out8[3]);
    up2(c2, out8[4], out8[5]);
    up2(c3, out8[6], out8[7]);
}

// ---------------------------------------------------------------------------
// Kernel 1: fused prep+pair. CTA (t,vv): A=W_{2t}^{c0}, B=W_{2t+1}^{c1} inline
// from theta/u, then P = A@B. grid=124, block=512.
// W_i^c[a,k] = sigmoid_c(theta[i,a,k]) * softmax(u[i])[k]
// ---------------------------------------------------------------------------
__global__ void __launch_bounds__(512) k_pair(const float* __restrict__ theta,
                                              const float* __restrict__ u) {
    __shared__ __align__(16) float sA[64 * AST4 * 4];
    __shared__ __align__(16) float sB[4096];
    __shared__ float expa[2][64];

    int blk = blockIdx.x, tid = threadIdx.x;
    int t = blk >> 2, vv = blk & 3;
    int i0 = 2 * t, i1 = 2 * t + 1, c0 = vv >> 1, c1 = vv & 1;
    int wid = tid >> 5, lane = tid & 31;

    if (wid < 2) {                               // softmax(u[i0]), softmax(u[i1])
        int i = i0 + wid;
        float u0 = u[i * 64 + lane], u1 = u[i * 64 + 32 + lane];
        float mm = fmaxf(u0, u1);
        #pragma unroll
        for (int o = 16; o; o >>= 1) mm = fmaxf(mm, __shfl_xor_sync(0xffffffffu, mm, o));
        float ss = __expf(u0 - mm) + __expf(u1 - mm);
        #pragma unroll
        for (int o = 16; o; o >>= 1) ss += __shfl_xor_sync(0xffffffffu, ss, o);
        float lse = mm + __logf(ss);
        expa[wid][lane]      = __expf(u0 - lse);
        expa[wid][lane + 32] = __expf(u1 - lse);
    }
    __syncthreads();

    const float4* th4 = reinterpret_cast<const float4*>(theta);
    float4* sA4 = reinterpret_cast<float4*>(sA);
    float4* sB4 = reinterpret_cast<float4*>(sB);
    #pragma unroll
    for (int r = 0; r < 2; ++r) {
        int idx4 = tid + 512 * r;                // float4 index 0..1023
        int row = idx4 >> 4, q = idx4 & 15;
        int k0 = q * 4;
        float4 ta = th4[i0 * 1024 + idx4];
        float4 oa;
        { float s = __fdividef(1.0f, 1.0f + __expf(-ta.x)); oa.x = (c0 ? s : 1.0f - s) * expa[0][k0 + 0]; }
        { float s = __fdividef(1.0f, 1.0f + __expf(-ta.y)); oa.y = (c0 ? s : 1.0f - s) * expa[0][k0 + 1]; }
        { float s = __fdividef(1.0f, 1.0f + __expf(-ta.z)); oa.z = (c0 ? s : 1.0f - s) * expa[0][k0 + 2]; }
        { float s = __fdividef(1.0f, 1.0f + __expf(-ta.w)); oa.w = (c0 ? s : 1.0f - s) * expa[0][k0 + 3]; }
        sA4[row * AST4 + q] = oa;
        float4 tb = th4[i1 * 1024 + idx4];
        float4 ob;
        { float s = __fdividef(1.0f, 1.0f + __expf(-tb.x)); ob.x = (c1 ? s : 1.0f - s) * expa[1][k0 + 0]; }
        { float s = __fdividef(1.0f, 1.0f + __expf(-tb.y)); ob.y = (c1 ? s : 1.0f - s) * expa[1][k0 + 1]; }
        { float s = __fdividef(1.0f, 1.0f + __expf(-tb.z)); ob.z = (c1 ? s : 1.0f - s) * expa[1][k0 + 2]; }
        { float s = __fdividef(1.0f, 1.0f + __expf(-tb.w)); ob.w = (c1 ? s : 1.0f - s) * expa[1][k0 + 3]; }
        sB4[idx4] = ob;
    }
    __syncthreads();

    int a = tid & 63, seg = tid >> 6;
    float acc[8];
    gemm_inner(sA4, sB4, a, seg, acc);

    float4* C4 = g_P4 + blk * 1024;
    C4[a * 16 + seg * 2]     = make_float4(acc[0], acc[1], acc[2], acc[3]);
    C4[a * 16 + seg * 2 + 1] = make_float4(acc[4], acc[5], acc[6], acc[7]);
}

// ---------------------------------------------------------------------------
// Kernel 2: quads Q = P_{2t}^{v>>2} @ P_{2t+1}^{v&3} (blk<240);
//           triples T = P_30^{v>>1} @ W62^{v&1} (blk 240..247, W62 inline).
// Output bf16 chunk layout for k_main. grid=248, block=512.
// ---------------------------------------------------------------------------
__global__ void __launch_bounds__(512) k_quad(const float* __restrict__ theta,
                                              const float* __restrict__ u) {
    __shared__ __align__(16) float sA[64 * AST4 * 4];
    __shared__ __align__(16) float sB[4096];
    __shared__ float expa[64];
    int blk = blockIdx.x, tid = threadIdx.x;

    float4* sA4 = reinterpret_cast<float4*>(sA);
    float4* sB4 = reinterpret_cast<float4*>(sB);

    if (blk < 240) {
        int t = blk >> 4, v = blk & 15;
        const float4* A4 = g_P4 + ((2 * t)     * 4 + (v >> 2)) * 1024;
        const float4* B4 = g_P4 + ((2 * t + 1) * 4 + (v & 3))  * 1024;
        #pragma unroll
        for (int r = 0; r < 2; ++r) {
            int idx4 = tid + 512 * r;            // = row*16 + q
            int row = idx4 >> 4, q = idx4 & 15;
            sA4[row * AST4 + q] = A4[idx4];
            sB4[idx4] = B4[idx4];
        }
    } else {
        int v = blk - 240;
        const float4* A4 = g_P4 + (30 * 4 + (v >> 1)) * 1024;
        #pragma unroll
        for (int r = 0; r < 2; ++r) {
            int idx4 = tid + 512 * r;
            int row = idx4 >> 4, q = idx4 & 15;
            sA4[row * AST4 + q] = A4[idx4];
        }
        int c = v & 1;
        if (tid < 32) {                          // softmax(u[62])
            float u0 = u[62 * 64 + tid], u1 = u[62 * 64 + 32 + tid];
            float mm = fmaxf(u0, u1);
            #pragma unroll
            for (int o = 16; o; o >>= 1) mm = fmaxf(mm, __shfl_xor_sync(0xffffffffu, mm, o));
            float ss = __expf(u0 - mm) + __expf(u1 - mm);
            #pragma unroll
            for (int o = 16; o; o >>= 1) ss += __shfl_xor_sync(0xffffffffu, ss, o);
            float lse = mm + __logf(ss);
            expa[tid]      = __expf(u0 - lse);
            expa[tid + 32] = __expf(u1 - lse);
        }
        __syncthreads();
        const float4* th4 = reinterpret_cast<const float4*>(theta);
        #pragma unroll
        for (int r = 0; r < 2; ++r) {
            int idx4 = tid + 512 * r;
            int k0 = (idx4 * 4) & 63;
            float4 tb = th4[62 * 1024 + idx4];
            float4 ob;
            { float s = __fdividef(1.0f, 1.0f + __expf(-tb.x)); ob.x = (c ? s : 1.0f - s) * expa[k0 + 0]; }
            { float s = __fdividef(1.0f, 1.0f + __expf(-tb.y)); ob.y = (c ? s : 1.0f - s) * expa[k0 + 1]; }
            { float s = __fdividef(1.0f, 1.0f + __expf(-tb.z)); ob.z = (c ? s : 1.0f - s) * expa[k0 + 2]; }
            { float s = __fdividef(1.0f, 1.0f + __expf(-tb.w)); ob.w = (c ? s : 1.0f - s) * expa[k0 + 3]; }
            sB4[idx4] = ob;
        }
    }
    __syncthreads();

    int a = tid & 63, seg = tid >> 6;
    float acc[8];
    gemm_inner(sA4, sB4, a, seg, acc);

    __nv_bfloat162 p0 = __floats2bfloat162_rn(acc[0], acc[1]);
    __nv_bfloat162 p1 = __floats2bfloat162_rn(acc[2], acc[3]);
    __nv_bfloat162 p2 = __floats2bfloat162_rn(acc[4], acc[5]);
    __nv_bfloat162 p3 = __floats2bfloat162_rn(acc[6], acc[7]);
    uint4 uo;
    uo.x = *reinterpret_cast<unsigned*>(&p0);
    uo.y = *reinterpret_cast<unsigned*>(&p1);
    uo.z = *reinterpret_cast<unsigned*>(&p2);
    uo.w = *reinterpret_cast<unsigned*>(&p3);
    g_Q4[blk * 512 + seg * 64 + a] = uo;
}

// ---------------------------------------------------------------------------
// Kernel 3: per-batch stabilized log-semiring chain, 16 steps. (unchanged)
// ---------------------------------------------------------------------------
__device__ __forceinline__ int matq(unsigned long long bits, int t) {
    unsigned nib = (unsigned)(bits >> (4 * t)) & 0xFu;
    unsigned v = ((nib & 1u) << 3) | ((nib & 2u) << 1) | ((nib & 4u) >> 1) | ((nib & 8u) >> 3);
    return t * 16 + (int)v;
}

__device__ __forceinline__ float dotstep(const uint4* wr, const float4* e4) {
    float a0 = 0.f, a1 = 0.f, a2 = 0.f, a3 = 0.f;
    float a4 = 0.f, a5 = 0.f, a6 = 0.f, a7 = 0.f;
    #pragma unroll
    for (int q = 0; q < 8; ++q) {
        float4 e0 = e4[2 * q], e1 = e4[2 * q + 1];
        uint4 uw = wr[q];
        a0 = fmaf(__uint_as_float(uw.x << 16),          e0.x, a0);
        a1 = fmaf(__uint_as_float(uw.x & 0xffff0000u),  e0.y, a1);
        a2 = fmaf(__uint_as_float(uw.y << 16),          e0.z, a2);
        a3 = fmaf(__uint_as_float(uw.y & 0xffff0000u),  e0.w, a3);
        a4 = fmaf(__uint_as_float(uw.z << 16),          e1.x, a4);
        a5 = fmaf(__uint_as_float(uw.z & 0xffff0000u),  e1.y, a5);
        a6 = fmaf(__uint_as_float(uw.w << 16),          e1.z, a6);
        a7 = fmaf(__uint_as_float(uw.w & 0xffff0000u),  e1.w, a7);
    }
    return ((a0 + a1) + (a2 + a3)) + ((a4 + a5) + (a6 + a7));
}

__global__ void __launch_bounds__(64) k_main(const float* __restrict__ x,
                                             const float* __restrict__ theta,
                                             float* __restrict__ out) {
    int tid = threadIdx.x, w = tid >> 5, l = tid & 31;
    int b = blockIdx.x;

    __shared__ __align__(16) float se[2][64];
    __shared__ float red[2];
    __shared__ unsigned sbits[2];

    float xa = x[b * 64 + tid];
    unsigned bal = __ballot_sync(0xffffffffu, xa != 0.0f);
    if (l == 0) sbits[w] = bal;
    __syncthreads();
    unsigned long long bits =
        ((unsigned long long)sbits[1] << 32) | (unsigned long long)sbits[0];

    // v init: log p(x63 | a, col 0)
    int c63 = (int)(bits >> 63) & 1;
    float t63 = theta[63 * 4096 + tid * 64];
    float v = (c63 ? t63 : 0.0f) - fmaxf(t63, 0.0f)
            - __logf(1.0f + __expf(-fabsf(t63)));

    // prefetch step 0 (triple)
    int m0 = 240 + (((int)(bits >> 60) & 1) << 2)
                 + (((int)(bits >> 61) & 1) << 1)
                 +  ((int)(bits >> 62) & 1);
    uint4 wrA[8], wrB[8];
    {
        const uint4* base = g_Q4 + m0 * 512;
        #pragma unroll
        for (int q = 0; q < 8; ++q) wrA[q] = base[q * 64 + tid];
    }

    float m = 0.0f;
    #pragma unroll 1
    for (int sp = 0; sp < 8; ++sp) {
        // ---- even step: compute with wrA, prefetch wrB, refresh max ----
        {
            const uint4* nb = g_Q4 + matq(bits, 14 - 2 * sp) * 512;
            #pragma unroll
            for (int q = 0; q < 8; ++q) wrB[q] = nb[q * 64 + tid];

            float wm = v;
            #pragma unroll
            for (int o = 16; o; o >>= 1) wm = fmaxf(wm, __shfl_xor_sync(0xffffffffu, wm, o));
            if (l == 0) red[w] = wm;
            __syncthreads();
            m = fmaxf(red[0], red[1]);
            se[0][tid] = __expf(v - m);
            __syncthreads();
            v = __logf(dotstep(wrA, reinterpret_cast<const float4*>(se[0]))) + m;
        }
        // ---- odd step: compute with wrB, prefetch wrA, stale max ----
        {
            if (sp < 7) {
                const uint4* nb = g_Q4 + matq(bits, 13 - 2 * sp) * 512;
                #pragma unroll
                for (int q = 0; q < 8; ++q) wrA[q] = nb[q * 64 + tid];
            }
            se[1][tid] = __expf(v - m);
            __syncthreads();
            v = __logf(dotstep(wrB, reinterpret_cast<const float4*>(se[1]))) + m;
        }
    }

    out[b * 64 + tid] = v;
}

// ---------------------------------------------------------------------------
extern "C" void kernel_launch(void* const* d_in, const int* in_sizes, int n_in,
                              void* d_out, int out_size) {
    const float* x     = nullptr;
    const float* theta = nullptr;
    const float* u     = nullptr;
    for (int i = 0; i < n_in; ++i) {
        if      (in_sizes[i] == BATCH * NIN)       x     = (const float*)d_in[i];
        else if (in_sizes[i] == NIN * ADIM * ADIM) theta = (const float*)d_in[i];
        else if (in_sizes[i] == (NIN - 1) * ADIM)  u     = (const float*)d_in[i];
    }

    k_pair<<<124, 512>>>(theta, u);
    k_quad<<<248, 512>>>(theta, u);
    k_main<<<BATCH, 64>>>(x, theta, (float*)d_out);
}